// round 12
// baseline (speedup 1.0000x reference)
#include <cuda_runtime.h>
#include <cuda_fp16.h>
#include <math.h>
#include <stdint.h>

#define NNODES 100000
#define NEDGES 640000
#define DD 128
#define SCAN_BLK 98            // ceil(100000/1024)
#define RSTRIDE 129            // u64 per A-tile row (pad: row groups land in distinct banks)
#define GEMM_SMEM (64 * RSTRIDE * 8)   // 66,048 B

// Scratch (__device__ globals: allocation-free rule)
__device__ __half g_conv_h[NNODES * DD];   // conv = nodes@W2 + b2 (UNSCALED), fp16
__device__ int    g_sdeg[NNODES];
__device__ int    g_rdeg[NNODES];
__device__ int    g_scan[NNODES];
__device__ int    g_bsum[SCAN_BLK];
__device__ int    g_boff[SCAN_BLK];
__device__ int    g_offs[NNODES];
__device__ int    g_cur[NNODES];
__device__ int    g_csr[NEDGES];
__device__ float  g_rss[NNODES];
__device__ float  g_gvec[DD];
__device__ float  g_an[DD];

// packed fp32x2 FMA
#define FMA_F32X2(acc, a, b) \
    asm("fma.rn.f32x2 %0, %1, %2, %0;" : "+l"(acc) : "l"(a), "l"(b))

__device__ __forceinline__ unsigned long long dup2(float f) {
    unsigned u = __float_as_uint(f);
    return (unsigned long long)u | ((unsigned long long)u << 32);
}
__device__ __forceinline__ float2 unpk(unsigned long long v) {
    return make_float2(__uint_as_float((unsigned)v), __uint_as_float((unsigned)(v >> 32)));
}

// ---------------------------------------------------------------- zero + gvec fused
__global__ void k_zero(const float* __restrict__ gl, const float* __restrict__ W3,
                       const float* __restrict__ b3) {
    int i = blockIdx.x * blockDim.x + threadIdx.x;
    if (i < NNODES) { g_sdeg[i] = 0; g_rdeg[i] = 0; }
    if (i < DD) g_an[i] = 0.f;
    if (blockIdx.x < DD) {
        __shared__ float red[DD];
        int c = blockIdx.x, t = threadIdx.x;
        if (t < DD) red[t] = gl[t] * W3[t * DD + c];
        __syncthreads();
        if (t < 64) red[t] += red[t + 64];
        __syncthreads();
        if (t < 32) {
            float v = red[t] + red[t + 32];
            #pragma unroll
            for (int o = 16; o > 0; o >>= 1) v += __shfl_down_sync(0xffffffff, v, o);
            if (t == 0) g_gvec[c] = v + b3[c];
        }
    }
}

// ---------------------------------------------------------------- degrees
__global__ void k_deg(const int* __restrict__ snd, const int* __restrict__ rcv) {
    int e = blockIdx.x * blockDim.x + threadIdx.x;
    if (e < NEDGES) {
        atomicAdd(&g_sdeg[snd[e]], 1);
        atomicAdd(&g_rdeg[rcv[e]], 1);
    }
}

// ---------------------------------------------------------------- prefix scan
__global__ __launch_bounds__(1024) void k_scanA() {
    __shared__ int sh[1024];
    int i = blockIdx.x * 1024 + threadIdx.x;
    int v = (i < NNODES) ? g_rdeg[i] : 0;
    sh[threadIdx.x] = v;
    __syncthreads();
    #pragma unroll
    for (int o = 1; o < 1024; o <<= 1) {
        int t = (threadIdx.x >= o) ? sh[threadIdx.x - o] : 0;
        __syncthreads();
        sh[threadIdx.x] += t;
        __syncthreads();
    }
    if (i < NNODES) g_scan[i] = sh[threadIdx.x];
    if (threadIdx.x == 1023) g_bsum[blockIdx.x] = sh[1023];
}
__global__ void k_scanB() {
    __shared__ int sh[128];
    int t = threadIdx.x;
    int v = (t < SCAN_BLK) ? g_bsum[t] : 0;
    sh[t] = v;
    __syncthreads();
    #pragma unroll
    for (int o = 1; o < 128; o <<= 1) {
        int u = (t >= o) ? sh[t - o] : 0;
        __syncthreads();
        sh[t] += u;
        __syncthreads();
    }
    if (t < SCAN_BLK) g_boff[t] = sh[t] - v;
}
__global__ void k_scanC() {
    int i = blockIdx.x * blockDim.x + threadIdx.x;
    if (i < NNODES) {
        int off = g_scan[i] - g_rdeg[i] + g_boff[i >> 10];
        g_offs[i] = off;
        g_cur[i]  = off;
        g_rss[i]  = rsqrtf(fmaxf((float)g_sdeg[i], 1.0f));
    }
}

// ---------------------------------------------------------------- CSR scatter
__global__ void k_scatter(const int* __restrict__ snd, const int* __restrict__ rcv) {
    int e = blockIdx.x * blockDim.x + threadIdx.x;
    if (e < NEDGES) {
        int r = rcv[e];
        int pos = atomicAdd(&g_cur[r], 1);
        g_csr[pos] = snd[e];
    }
}

// ---------------------------------------------------------------- f32x2 GEMM v3 (4x16 register tile)
// 128 thr/block, 64-row tile. Warp: rg=lane>>3 (4 row groups x 4 rows), c=lane&7.
// Thread cols: 4 chunks of 4 at stride 32 (q*32 + c*4) -> each W LDG.128 is one
// contiguous 128B line across the 8 c-lanes = 1 wavefront.
// Per k per thread: 4 LDS.64 + 4 LDG.128 + 32 FFMA2  (8 wavefronts vs 12 in v2).
extern __shared__ unsigned long long As2[];   // [64][RSTRIDE] u64
__global__ __launch_bounds__(128) void k_gemm(
    const float* __restrict__ A,
    const float* __restrict__ W1, const float* __restrict__ b1,
    const float* __restrict__ W2, const float* __restrict__ b2,
    float* __restrict__ out_h)
{
    const int which = blockIdx.y;
    const float* W    = which ? W2 : W1;
    const float* bias = which ? b2 : b1;
    const int rowBase = blockIdx.x * 64;
    const int tid = threadIdx.x;
    const int maxr = NNODES - rowBase;

    // Load + duplicate A tile [64 x 128] (2048 float4, 16 iters)
    const float4* A4 = (const float4*)(A + (long)rowBase * DD);
    #pragma unroll
    for (int i = 0; i < 16; i++) {
        int idx4 = tid + i * 128;
        int row = idx4 >> 5, col4 = (idx4 & 31) << 2;
        float4 v = make_float4(0.f, 0.f, 0.f, 0.f);
        if (row < maxr) v = A4[idx4];
        unsigned long long* d = &As2[row * RSTRIDE + col4];
        d[0] = dup2(v.x); d[1] = dup2(v.y); d[2] = dup2(v.z); d[3] = dup2(v.w);
    }
    __syncthreads();

    const int lane = tid & 31;
    const int wz   = tid >> 5;        // warp 0..3
    const int rg   = lane >> 3;       // row group 0..3 (4 rows each)
    const int c    = lane & 7;        // col lane: chunks q*32 + c*4
    const int rowB = wz * 16 + rg * 4;

    unsigned long long acc[4][8];     // [row][q*2+half] = 32 u64
    #pragma unroll
    for (int i = 0; i < 4; i++)
        #pragma unroll
        for (int q = 0; q < 8; q++) acc[i][q] = 0ull;

    const unsigned long long* Asrow = &As2[rowB * RSTRIDE];
    const float* Wc = W + c * 4;
    #pragma unroll 4
    for (int k = 0; k < DD; k++) {
        const float* Wk = Wc + (long)k * DD;
        ulonglong2 w0 = *(const ulonglong2*)(Wk);           // cols  0+c*4 .. +3
        ulonglong2 w1 = *(const ulonglong2*)(Wk + 32);      // cols 32+c*4 .. +3
        ulonglong2 w2 = *(const ulonglong2*)(Wk + 64);      // cols 64+c*4 .. +3
        ulonglong2 w3 = *(const ulonglong2*)(Wk + 96);      // cols 96+c*4 .. +3
        #pragma unroll
        for (int i = 0; i < 4; i++) {
            unsigned long long ap = Asrow[i * RSTRIDE + k];   // 4-addr broadcast LDS.64
            FMA_F32X2(acc[i][0], ap, w0.x);
            FMA_F32X2(acc[i][1], ap, w0.y);
            FMA_F32X2(acc[i][2], ap, w1.x);
            FMA_F32X2(acc[i][3], ap, w1.y);
            FMA_F32X2(acc[i][4], ap, w2.x);
            FMA_F32X2(acc[i][5], ap, w2.y);
            FMA_F32X2(acc[i][6], ap, w3.x);
            FMA_F32X2(acc[i][7], ap, w3.y);
        }
    }

    #pragma unroll
    for (int i = 0; i < 4; i++) {
        int r = rowB + i;
        if (r < maxr) {
            int gr = rowBase + r;
            #pragma unroll
            for (int q = 0; q < 4; q++) {
                int cb = q * 32 + c * 4;
                float4 bv = *(const float4*)(bias + cb);
                float2 p0 = unpk(acc[i][q * 2]);
                float2 p1 = unpk(acc[i][q * 2 + 1]);
                float4 o = make_float4(p0.x + bv.x, p0.y + bv.y, p1.x + bv.z, p1.y + bv.w);
                if (which) {
                    __half2 h01 = __floats2half2_rn(o.x, o.y);
                    __half2 h23 = __floats2half2_rn(o.z, o.w);
                    uint2 pk;
                    pk.x = *(unsigned*)&h01; pk.y = *(unsigned*)&h23;
                    *(uint2*)&g_conv_h[(long)gr * DD + cb] = pk;
                } else {
                    *(float4*)(out_h + (long)gr * DD + cb) = o;
                }
            }
        }
    }
}

// ---------------------------------------------------------------- CSR pull + fused epilogue
__global__ __launch_bounds__(256) void k_gather(const float* __restrict__ nodes,
                                                float* __restrict__ out) {
    __shared__ float4 sred[256];
    const int tid  = threadIdx.x;
    const int lane = tid & 31;
    const int wy   = tid >> 5;
    const int r    = blockIdx.x * 8 + wy;
    float4 sum = make_float4(0.f, 0.f, 0.f, 0.f);

    if (r < NNODES) {
        const int start = g_offs[r];
        const int deg   = g_rdeg[r];
        float4 acc = make_float4(0.f, 0.f, 0.f, 0.f);
        int j = 0;
        for (; j + 1 < deg; j += 2) {
            int s0 = g_csr[start + j];
            int s1 = g_csr[start + j + 1];
            float w0 = g_rss[s0];
            float w1 = g_rss[s1];
            uint2 a0 = *(const uint2*)&g_conv_h[(long)s0 * DD + lane * 4];
            uint2 a1 = *(const uint2*)&g_conv_h[(long)s1 * DD + lane * 4];
            float2 p00 = __half22float2(*(__half2*)&a0.x);
            float2 p01 = __half22float2(*(__half2*)&a0.y);
            float2 p10 = __half22float2(*(__half2*)&a1.x);
            float2 p11 = __half22float2(*(__half2*)&a1.y);
            acc.x = fmaf(p00.x, w0, fmaf(p10.x, w1, acc.x));
            acc.y = fmaf(p00.y, w0, fmaf(p10.y, w1, acc.y));
            acc.z = fmaf(p01.x, w0, fmaf(p11.x, w1, acc.z));
            acc.w = fmaf(p01.y, w0, fmaf(p11.y, w1, acc.w));
        }
        if (j < deg) {
            int s0 = g_csr[start + j];
            float w0 = g_rss[s0];
            uint2 a0 = *(const uint2*)&g_conv_h[(long)s0 * DD + lane * 4];
            float2 p00 = __half22float2(*(__half2*)&a0.x);
            float2 p01 = __half22float2(*(__half2*)&a0.y);
            acc.x = fmaf(p00.x, w0, acc.x);
            acc.y = fmaf(p00.y, w0, acc.y);
            acc.z = fmaf(p01.x, w0, acc.z);
            acc.w = fmaf(p01.y, w0, acc.w);
        }
        float rs = rsqrtf(fmaxf((float)deg, 1.0f));
        float4 gv = ((const float4*)g_gvec)[lane];
        long off = (long)r * 32 + lane;
        float4 h  = ((float4*)out)[off];
        float4 nd = ((const float4*)nodes)[off];
        float4 o;
        o.x = fmaxf(h.x + acc.x * rs + gv.x, 0.f) + nd.x;
        o.y = fmaxf(h.y + acc.y * rs + gv.y, 0.f) + nd.y;
        o.z = fmaxf(h.z + acc.z * rs + gv.z, 0.f) + nd.z;
        o.w = fmaxf(h.w + acc.w * rs + gv.w, 0.f) + nd.w;
        ((float4*)out)[off] = o;
        sum = o;
    }
    sred[tid] = sum;
    __syncthreads();
    if (wy == 0) {
        float4 s = sred[lane];
        #pragma unroll
        for (int jj = 1; jj < 8; jj++) {
            float4 t = sred[jj * 32 + lane];
            s.x += t.x; s.y += t.y; s.z += t.z; s.w += t.w;
        }
        float* addr = &g_an[lane * 4];
        asm volatile("red.global.add.v4.f32 [%0], {%1,%2,%3,%4};"
                     :: "l"(addr), "f"(s.x), "f"(s.y), "f"(s.z), "f"(s.w)
                     : "memory");
    }
}

// ---------------------------------------------------------------- global update
__global__ void k_global(const float* __restrict__ gl, const float* __restrict__ Wg,
                         const float* __restrict__ bg, float* __restrict__ outg) {
    __shared__ float red[2 * DD];
    int c = blockIdx.x, t = threadIdx.x;
    float x = (t < DD) ? g_an[t] : gl[t - DD];
    red[t] = x * Wg[t * DD + c];
    __syncthreads();
    if (t < 128) red[t] += red[t + 128];
    __syncthreads();
    if (t < 64) red[t] += red[t + 64];
    __syncthreads();
    if (t < 32) {
        float v = red[t] + red[t + 32];
        #pragma unroll
        for (int o = 16; o > 0; o >>= 1) v += __shfl_down_sync(0xffffffff, v, o);
        if (t == 0) outg[c] = gl[c] + fmaxf(v + bg[c], 0.f);
    }
}

// ---------------------------------------------------------------- launch (forked graph)
extern "C" void kernel_launch(void* const* d_in, const int* in_sizes, int n_in,
                              void* d_out, int out_size) {
    const float* nodes    = (const float*)d_in[0];
    const float* globals_ = (const float*)d_in[1];
    const int*   senders   = (const int*)d_in[2];
    const int*   receivers = (const int*)d_in[3];
    const float* W1w = (const float*)d_in[4];
    const float* W1b = (const float*)d_in[5];
    const float* W2w = (const float*)d_in[6];
    const float* W2b = (const float*)d_in[7];
    const float* W3w = (const float*)d_in[8];
    const float* W3b = (const float*)d_in[9];
    const float* Wgw = (const float*)d_in[10];
    const float* Wgb = (const float*)d_in[11];
    float* out = (float*)d_out;

    static cudaStream_t s1 = nullptr;
    static cudaEvent_t evRoot = nullptr, evSide = nullptr;
    if (s1 == nullptr) {
        cudaFuncSetAttribute(k_gemm, cudaFuncAttributeMaxDynamicSharedMemorySize, GEMM_SMEM);
        cudaStreamCreateWithFlags(&s1, cudaStreamNonBlocking);
        cudaEventCreateWithFlags(&evRoot, cudaEventDisableTiming);
        cudaEventCreateWithFlags(&evSide, cudaEventDisableTiming);
    }

    // fork
    cudaEventRecord(evRoot, 0);
    cudaStreamWaitEvent(s1, evRoot, 0);

    // side chain part 1 (s1): submissions #1-#3
    k_zero<<<(NNODES + 255) / 256, 256, 0, s1>>>(globals_, W3w, W3b);
    k_deg<<<(NEDGES + 255) / 256, 256, 0, s1>>>(senders, receivers);
    k_scanA<<<SCAN_BLK, 1024, 0, s1>>>();

    // main: dual GEMM — submission #4 (profiler target)
    dim3 gg((NNODES + 63) / 64, 2);
    k_gemm<<<gg, 128, GEMM_SMEM>>>(nodes, W1w, W1b, W2w, W2b, out);

    // side chain part 2 (s1)
    k_scanB<<<1, 128, 0, s1>>>();
    k_scanC<<<(NNODES + 255) / 256, 256, 0, s1>>>();
    k_scatter<<<(NEDGES + 255) / 256, 256, 0, s1>>>(senders, receivers);
    cudaEventRecord(evSide, s1);

    // join -> pull-aggregate + fused epilogue -> global update
    cudaStreamWaitEvent(0, evSide, 0);
    k_gather<<<(NNODES + 7) / 8, 256>>>(nodes, out);
    k_global<<<DD, 2 * DD>>>(globals_, Wgw, Wgb, out + (long)NNODES * DD);
}

// round 13
// speedup vs baseline: 1.0468x; 1.0468x over previous
#include <cuda_runtime.h>
#include <cuda_fp16.h>
#include <math.h>
#include <stdint.h>

#define NNODES 100000
#define NEDGES 640000
#define DD 128
#define SCAN_BLK 98            // ceil(100000/1024)
#define TROWS 48               // GEMM tile rows (4 blocks/SM: 49.5KB smem each)
#define RSTRIDE 129            // u64 per A-tile row (bank pad)
#define GEMM_SMEM (TROWS * RSTRIDE * 8)   // 49,536 B

// Scratch (__device__ globals: allocation-free rule)
__device__ __half g_conv_h[NNODES * DD];   // conv = nodes@W2 + b2 (UNSCALED), fp16
__device__ int    g_sdeg[NNODES];
__device__ int    g_rdeg[NNODES];
__device__ int    g_scan[NNODES];
__device__ int    g_bsum[SCAN_BLK];
__device__ int    g_boff[SCAN_BLK];
__device__ int    g_offs[NNODES];
__device__ int    g_cur[NNODES];
__device__ int    g_csr[NEDGES];
__device__ float  g_rss[NNODES];
__device__ float  g_gvec[DD];
__device__ float  g_an[DD];

// packed fp32x2 FMA
#define FMA_F32X2(acc, a, b) \
    asm("fma.rn.f32x2 %0, %1, %2, %0;" : "+l"(acc) : "l"(a), "l"(b))

__device__ __forceinline__ unsigned long long dup2(float f) {
    unsigned u = __float_as_uint(f);
    return (unsigned long long)u | ((unsigned long long)u << 32);
}
__device__ __forceinline__ float2 unpk(unsigned long long v) {
    return make_float2(__uint_as_float((unsigned)v), __uint_as_float((unsigned)(v >> 32)));
}

// ---------------------------------------------------------------- zero + gvec fused
__global__ void k_zero(const float* __restrict__ gl, const float* __restrict__ W3,
                       const float* __restrict__ b3) {
    int i = blockIdx.x * blockDim.x + threadIdx.x;
    if (i < NNODES) { g_sdeg[i] = 0; g_rdeg[i] = 0; }
    if (i < DD) g_an[i] = 0.f;
    if (blockIdx.x < DD) {
        __shared__ float red[DD];
        int c = blockIdx.x, t = threadIdx.x;
        if (t < DD) red[t] = gl[t] * W3[t * DD + c];
        __syncthreads();
        if (t < 64) red[t] += red[t + 64];
        __syncthreads();
        if (t < 32) {
            float v = red[t] + red[t + 32];
            #pragma unroll
            for (int o = 16; o > 0; o >>= 1) v += __shfl_down_sync(0xffffffff, v, o);
            if (t == 0) g_gvec[c] = v + b3[c];
        }
    }
}

// ---------------------------------------------------------------- degrees
__global__ void k_deg(const int* __restrict__ snd, const int* __restrict__ rcv) {
    int e = blockIdx.x * blockDim.x + threadIdx.x;
    if (e < NEDGES) {
        atomicAdd(&g_sdeg[snd[e]], 1);
        atomicAdd(&g_rdeg[rcv[e]], 1);
    }
}

// ---------------------------------------------------------------- prefix scan
__global__ __launch_bounds__(1024) void k_scanA() {
    __shared__ int sh[1024];
    int i = blockIdx.x * 1024 + threadIdx.x;
    int v = (i < NNODES) ? g_rdeg[i] : 0;
    sh[threadIdx.x] = v;
    __syncthreads();
    #pragma unroll
    for (int o = 1; o < 1024; o <<= 1) {
        int t = (threadIdx.x >= o) ? sh[threadIdx.x - o] : 0;
        __syncthreads();
        sh[threadIdx.x] += t;
        __syncthreads();
    }
    if (i < NNODES) g_scan[i] = sh[threadIdx.x];
    if (threadIdx.x == 1023) g_bsum[blockIdx.x] = sh[1023];
}
__global__ void k_scanB() {
    __shared__ int sh[128];
    int t = threadIdx.x;
    int v = (t < SCAN_BLK) ? g_bsum[t] : 0;
    sh[t] = v;
    __syncthreads();
    #pragma unroll
    for (int o = 1; o < 128; o <<= 1) {
        int u = (t >= o) ? sh[t - o] : 0;
        __syncthreads();
        sh[t] += u;
        __syncthreads();
    }
    if (t < SCAN_BLK) g_boff[t] = sh[t] - v;
}
__global__ void k_scanC() {
    int i = blockIdx.x * blockDim.x + threadIdx.x;
    if (i < NNODES) {
        int off = g_scan[i] - g_rdeg[i] + g_boff[i >> 10];
        g_offs[i] = off;
        g_cur[i]  = off;
        g_rss[i]  = rsqrtf(fmaxf((float)g_sdeg[i], 1.0f));
    }
}

// ---------------------------------------------------------------- CSR scatter
__global__ void k_scatter(const int* __restrict__ snd, const int* __restrict__ rcv) {
    int e = blockIdx.x * blockDim.x + threadIdx.x;
    if (e < NEDGES) {
        int r = rcv[e];
        int pos = atomicAdd(&g_cur[r], 1);
        g_csr[pos] = snd[e];
    }
}

// ---------------------------------------------------------------- f32x2 GEMM v4 (v2 mix @ 16 warps/SM)
// 128 thr/block, 48-row tile, 4 blocks/SM. Warp = 12 rows x 128 cols:
// rg=lane>>4 (2 groups of 6 rows), c=lane&15 (cols c*8..c*8+7).
// Per k per thread: 6 LDS.64 + 2 LDG.128 + 24 FFMA2 (same 4:1 mix as v2).
extern __shared__ unsigned long long As2[];   // [TROWS][RSTRIDE] u64
__global__ __launch_bounds__(128, 4) void k_gemm(
    const float* __restrict__ A,
    const float* __restrict__ W1, const float* __restrict__ b1,
    const float* __restrict__ W2, const float* __restrict__ b2,
    float* __restrict__ out_h)
{
    const int which = blockIdx.y;
    const float* W    = which ? W2 : W1;
    const float* bias = which ? b2 : b1;
    const int rowBase = blockIdx.x * TROWS;
    const int tid = threadIdx.x;
    const int maxr = NNODES - rowBase;

    // Load + duplicate A tile [48 x 128] (1536 float4, 12 iters)
    const float4* A4 = (const float4*)(A + (long)rowBase * DD);
    #pragma unroll
    for (int i = 0; i < 12; i++) {
        int idx4 = tid + i * 128;
        int row = idx4 >> 5, col4 = (idx4 & 31) << 2;
        float4 v = make_float4(0.f, 0.f, 0.f, 0.f);
        if (row < maxr) v = A4[idx4];
        unsigned long long* d = &As2[row * RSTRIDE + col4];
        d[0] = dup2(v.x); d[1] = dup2(v.y); d[2] = dup2(v.z); d[3] = dup2(v.w);
    }
    __syncthreads();

    const int lane = tid & 31;
    const int wz   = tid >> 5;        // warp 0..3
    const int rg   = lane >> 4;       // row group 0/1 (6 rows each)
    const int c    = lane & 15;       // col group: cols c*8 .. c*8+7
    const int rowB = wz * 12 + rg * 6;

    unsigned long long acc[6][4];
    #pragma unroll
    for (int i = 0; i < 6; i++)
        { acc[i][0] = 0ull; acc[i][1] = 0ull; acc[i][2] = 0ull; acc[i][3] = 0ull; }

    const unsigned long long* Asrow = &As2[rowB * RSTRIDE];
    const float* Wc = W + c * 8;
    #pragma unroll 8
    for (int k = 0; k < DD; k++) {
        ulonglong2 wp0 = *(const ulonglong2*)(Wc + (long)k * DD);      // cols c*8..+3
        ulonglong2 wp1 = *(const ulonglong2*)(Wc + (long)k * DD + 4);  // cols c*8+4..+7
        #pragma unroll
        for (int i = 0; i < 6; i++) {
            unsigned long long ap = Asrow[i * RSTRIDE + k];            // 2-addr broadcast LDS.64
            FMA_F32X2(acc[i][0], ap, wp0.x);
            FMA_F32X2(acc[i][1], ap, wp0.y);
            FMA_F32X2(acc[i][2], ap, wp1.x);
            FMA_F32X2(acc[i][3], ap, wp1.y);
        }
    }

    float4 bv0 = *(const float4*)(bias + c * 8);
    float4 bv1 = *(const float4*)(bias + c * 8 + 4);
    #pragma unroll
    for (int i = 0; i < 6; i++) {
        int r = rowB + i;
        if (r < maxr) {
            int gr = rowBase + r;
            float2 p0 = unpk(acc[i][0]);
            float2 p1 = unpk(acc[i][1]);
            float2 p2 = unpk(acc[i][2]);
            float2 p3 = unpk(acc[i][3]);
            float4 oa = make_float4(p0.x + bv0.x, p0.y + bv0.y, p1.x + bv0.z, p1.y + bv0.w);
            float4 ob = make_float4(p2.x + bv1.x, p2.y + bv1.y, p3.x + bv1.z, p3.y + bv1.w);
            if (which) {
                __half2 h0 = __floats2half2_rn(oa.x, oa.y);
                __half2 h1 = __floats2half2_rn(oa.z, oa.w);
                __half2 h2 = __floats2half2_rn(ob.x, ob.y);
                __half2 h3 = __floats2half2_rn(ob.z, ob.w);
                uint4 pk;
                pk.x = *(unsigned*)&h0; pk.y = *(unsigned*)&h1;
                pk.z = *(unsigned*)&h2; pk.w = *(unsigned*)&h3;
                *(uint4*)&g_conv_h[(long)gr * DD + c * 8] = pk;
            } else {
                *(float4*)(out_h + (long)gr * DD + c * 8)     = oa;
                *(float4*)(out_h + (long)gr * DD + c * 8 + 4) = ob;
            }
        }
    }
}

// ---------------------------------------------------------------- CSR pull + fused epilogue
__global__ __launch_bounds__(256) void k_gather(const float* __restrict__ nodes,
                                                float* __restrict__ out) {
    __shared__ float4 sred[256];
    const int tid  = threadIdx.x;
    const int lane = tid & 31;
    const int wy   = tid >> 5;
    const int r    = blockIdx.x * 8 + wy;
    float4 sum = make_float4(0.f, 0.f, 0.f, 0.f);

    if (r < NNODES) {
        const int start = g_offs[r];
        const int deg   = g_rdeg[r];
        float4 acc = make_float4(0.f, 0.f, 0.f, 0.f);
        int j = 0;
        for (; j + 1 < deg; j += 2) {
            int s0 = g_csr[start + j];
            int s1 = g_csr[start + j + 1];
            float w0 = g_rss[s0];
            float w1 = g_rss[s1];
            uint2 a0 = *(const uint2*)&g_conv_h[(long)s0 * DD + lane * 4];
            uint2 a1 = *(const uint2*)&g_conv_h[(long)s1 * DD + lane * 4];
            float2 p00 = __half22float2(*(__half2*)&a0.x);
            float2 p01 = __half22float2(*(__half2*)&a0.y);
            float2 p10 = __half22float2(*(__half2*)&a1.x);
            float2 p11 = __half22float2(*(__half2*)&a1.y);
            acc.x = fmaf(p00.x, w0, fmaf(p10.x, w1, acc.x));
            acc.y = fmaf(p00.y, w0, fmaf(p10.y, w1, acc.y));
            acc.z = fmaf(p01.x, w0, fmaf(p11.x, w1, acc.z));
            acc.w = fmaf(p01.y, w0, fmaf(p11.y, w1, acc.w));
        }
        if (j < deg) {
            int s0 = g_csr[start + j];
            float w0 = g_rss[s0];
            uint2 a0 = *(const uint2*)&g_conv_h[(long)s0 * DD + lane * 4];
            float2 p00 = __half22float2(*(__half2*)&a0.x);
            float2 p01 = __half22float2(*(__half2*)&a0.y);
            acc.x = fmaf(p00.x, w0, acc.x);
            acc.y = fmaf(p00.y, w0, acc.y);
            acc.z = fmaf(p01.x, w0, acc.z);
            acc.w = fmaf(p01.y, w0, acc.w);
        }
        float rs = rsqrtf(fmaxf((float)deg, 1.0f));
        float4 gv = ((const float4*)g_gvec)[lane];
        long off = (long)r * 32 + lane;
        float4 h  = ((float4*)out)[off];
        float4 nd = ((const float4*)nodes)[off];
        float4 o;
        o.x = fmaxf(h.x + acc.x * rs + gv.x, 0.f) + nd.x;
        o.y = fmaxf(h.y + acc.y * rs + gv.y, 0.f) + nd.y;
        o.z = fmaxf(h.z + acc.z * rs + gv.z, 0.f) + nd.z;
        o.w = fmaxf(h.w + acc.w * rs + gv.w, 0.f) + nd.w;
        ((float4*)out)[off] = o;
        sum = o;
    }
    sred[tid] = sum;
    __syncthreads();
    if (wy == 0) {
        float4 s = sred[lane];
        #pragma unroll
        for (int jj = 1; jj < 8; jj++) {
            float4 t = sred[jj * 32 + lane];
            s.x += t.x; s.y += t.y; s.z += t.z; s.w += t.w;
        }
        float* addr = &g_an[lane * 4];
        asm volatile("red.global.add.v4.f32 [%0], {%1,%2,%3,%4};"
                     :: "l"(addr), "f"(s.x), "f"(s.y), "f"(s.z), "f"(s.w)
                     : "memory");
    }
}

// ---------------------------------------------------------------- global update
__global__ void k_global(const float* __restrict__ gl, const float* __restrict__ Wg,
                         const float* __restrict__ bg, float* __restrict__ outg) {
    __shared__ float red[2 * DD];
    int c = blockIdx.x, t = threadIdx.x;
    float x = (t < DD) ? g_an[t] : gl[t - DD];
    red[t] = x * Wg[t * DD + c];
    __syncthreads();
    if (t < 128) red[t] += red[t + 128];
    __syncthreads();
    if (t < 64) red[t] += red[t + 64];
    __syncthreads();
    if (t < 32) {
        float v = red[t] + red[t + 32];
        #pragma unroll
        for (int o = 16; o > 0; o >>= 1) v += __shfl_down_sync(0xffffffff, v, o);
        if (t == 0) outg[c] = gl[c] + fmaxf(v + bg[c], 0.f);
    }
}

// ---------------------------------------------------------------- launch (forked graph)
extern "C" void kernel_launch(void* const* d_in, const int* in_sizes, int n_in,
                              void* d_out, int out_size) {
    const float* nodes    = (const float*)d_in[0];
    const float* globals_ = (const float*)d_in[1];
    const int*   senders   = (const int*)d_in[2];
    const int*   receivers = (const int*)d_in[3];
    const float* W1w = (const float*)d_in[4];
    const float* W1b = (const float*)d_in[5];
    const float* W2w = (const float*)d_in[6];
    const float* W2b = (const float*)d_in[7];
    const float* W3w = (const float*)d_in[8];
    const float* W3b = (const float*)d_in[9];
    const float* Wgw = (const float*)d_in[10];
    const float* Wgb = (const float*)d_in[11];
    float* out = (float*)d_out;

    static cudaStream_t s1 = nullptr;
    static cudaEvent_t evRoot = nullptr, evSide = nullptr;
    if (s1 == nullptr) {
        cudaFuncSetAttribute(k_gemm, cudaFuncAttributeMaxDynamicSharedMemorySize, GEMM_SMEM);
        cudaStreamCreateWithFlags(&s1, cudaStreamNonBlocking);
        cudaEventCreateWithFlags(&evRoot, cudaEventDisableTiming);
        cudaEventCreateWithFlags(&evSide, cudaEventDisableTiming);
    }

    // fork
    cudaEventRecord(evRoot, 0);
    cudaStreamWaitEvent(s1, evRoot, 0);

    // side chain part 1 (s1): submissions #1-#3
    k_zero<<<(NNODES + 255) / 256, 256, 0, s1>>>(globals_, W3w, W3b);
    k_deg<<<(NEDGES + 255) / 256, 256, 0, s1>>>(senders, receivers);
    k_scanA<<<SCAN_BLK, 1024, 0, s1>>>();

    // main: dual GEMM — submission #4 (profiler target)
    dim3 gg((NNODES + TROWS - 1) / TROWS, 2);
    k_gemm<<<gg, 128, GEMM_SMEM>>>(nodes, W1w, W1b, W2w, W2b, out);

    // side chain part 2 (s1)
    k_scanB<<<1, 128, 0, s1>>>();
    k_scanC<<<(NNODES + 255) / 256, 256, 0, s1>>>();
    k_scatter<<<(NEDGES + 255) / 256, 256, 0, s1>>>(senders, receivers);
    cudaEventRecord(evSide, s1);

    // join -> pull-aggregate + fused epilogue -> global update
    cudaStreamWaitEvent(0, evSide, 0);
    k_gather<<<(NNODES + 7) / 8, 256>>>(nodes, out);
    k_global<<<DD, 2 * DD>>>(globals_, Wgw, Wgb, out + (long)NNODES * DD);
}

// round 14
// speedup vs baseline: 1.1060x; 1.0566x over previous
#include <cuda_runtime.h>
#include <cuda_fp16.h>
#include <math.h>
#include <stdint.h>

#define NNODES 100000
#define NEDGES 640000
#define DD 128
#define SCAN_BLK 98            // ceil(100000/1024)
#define KP 64                  // k-pairs
#define PROWS 65               // padded rows per k2 slab (8-way fill conflicts, 0-way mainloop)
#define GEMM_SMEM (KP * PROWS * 16)   // 66,560 B -> 3 blocks/SM

// Scratch (__device__ globals: allocation-free rule)
__device__ __half g_conv_h[NNODES * DD];   // conv = nodes@W2 + b2 (UNSCALED), fp16
__device__ int    g_sdeg[NNODES];
__device__ int    g_rdeg[NNODES];
__device__ int    g_scan[NNODES];
__device__ int    g_bsum[SCAN_BLK];
__device__ int    g_boff[SCAN_BLK];
__device__ int    g_offs[NNODES];
__device__ int    g_cur[NNODES];
__device__ int    g_csr[NEDGES];
__device__ float  g_rss[NNODES];
__device__ float  g_gvec[DD];
__device__ float  g_an[DD];

// packed fp32x2 FMA
#define FMA_F32X2(acc, a, b) \
    asm("fma.rn.f32x2 %0, %1, %2, %0;" : "+l"(acc) : "l"(a), "l"(b))

__device__ __forceinline__ unsigned long long dup2(float f) {
    unsigned u = __float_as_uint(f);
    return (unsigned long long)u | ((unsigned long long)u << 32);
}
__device__ __forceinline__ float2 unpk(unsigned long long v) {
    return make_float2(__uint_as_float((unsigned)v), __uint_as_float((unsigned)(v >> 32)));
}

// ---------------------------------------------------------------- zero + gvec fused
__global__ void k_zero(const float* __restrict__ gl, const float* __restrict__ W3,
                       const float* __restrict__ b3) {
    int i = blockIdx.x * blockDim.x + threadIdx.x;
    if (i < NNODES) { g_sdeg[i] = 0; g_rdeg[i] = 0; }
    if (i < DD) g_an[i] = 0.f;
    if (blockIdx.x < DD) {
        __shared__ float red[DD];
        int c = blockIdx.x, t = threadIdx.x;
        if (t < DD) red[t] = gl[t] * W3[t * DD + c];
        __syncthreads();
        if (t < 64) red[t] += red[t + 64];
        __syncthreads();
        if (t < 32) {
            float v = red[t] + red[t + 32];
            #pragma unroll
            for (int o = 16; o > 0; o >>= 1) v += __shfl_down_sync(0xffffffff, v, o);
            if (t == 0) g_gvec[c] = v + b3[c];
        }
    }
}

// ---------------------------------------------------------------- degrees
__global__ void k_deg(const int* __restrict__ snd, const int* __restrict__ rcv) {
    int e = blockIdx.x * blockDim.x + threadIdx.x;
    if (e < NEDGES) {
        atomicAdd(&g_sdeg[snd[e]], 1);
        atomicAdd(&g_rdeg[rcv[e]], 1);
    }
}

// ---------------------------------------------------------------- prefix scan
__global__ __launch_bounds__(1024) void k_scanA() {
    __shared__ int sh[1024];
    int i = blockIdx.x * 1024 + threadIdx.x;
    int v = (i < NNODES) ? g_rdeg[i] : 0;
    sh[threadIdx.x] = v;
    __syncthreads();
    #pragma unroll
    for (int o = 1; o < 1024; o <<= 1) {
        int t = (threadIdx.x >= o) ? sh[threadIdx.x - o] : 0;
        __syncthreads();
        sh[threadIdx.x] += t;
        __syncthreads();
    }
    if (i < NNODES) g_scan[i] = sh[threadIdx.x];
    if (threadIdx.x == 1023) g_bsum[blockIdx.x] = sh[1023];
}
__global__ void k_scanB() {
    __shared__ int sh[128];
    int t = threadIdx.x;
    int v = (t < SCAN_BLK) ? g_bsum[t] : 0;
    sh[t] = v;
    __syncthreads();
    #pragma unroll
    for (int o = 1; o < 128; o <<= 1) {
        int u = (t >= o) ? sh[t - o] : 0;
        __syncthreads();
        sh[t] += u;
        __syncthreads();
    }
    if (t < SCAN_BLK) g_boff[t] = sh[t] - v;
}
__global__ void k_scanC() {
    int i = blockIdx.x * blockDim.x + threadIdx.x;
    if (i < NNODES) {
        int off = g_scan[i] - g_rdeg[i] + g_boff[i >> 10];
        g_offs[i] = off;
        g_cur[i]  = off;
        g_rss[i]  = rsqrtf(fmaxf((float)g_sdeg[i], 1.0f));
    }
}

// ---------------------------------------------------------------- CSR scatter
__global__ void k_scatter(const int* __restrict__ snd, const int* __restrict__ rcv) {
    int e = blockIdx.x * blockDim.x + threadIdx.x;
    if (e < NEDGES) {
        int r = rcv[e];
        int pos = atomicAdd(&g_cur[r], 1);
        g_csr[pos] = snd[e];
    }
}

// ---------------------------------------------------------------- f32x2 GEMM v5 (k-paired LDS.128)
// 128 thr/block, 64-row tile, 3 blocks/SM. A tile stored k-pair-major:
// 16B entry (k2,row) = (dup(a[2k2]), dup(a[2k2+1])) at u64 index (k2*PROWS+row)*2.
// Warp: rg=lane>>4, c=lane&15; thread rows = wz*16 + rg + 2i (i=0..7).
// Per 2k per thread: 8 LDS.128 + 4 LDG.128 + 64 FFMA2 (16 wf vs v2's 24).
extern __shared__ unsigned long long As2[];
__global__ __launch_bounds__(128) void k_gemm(
    const float* __restrict__ A,
    const float* __restrict__ W1, const float* __restrict__ b1,
    const float* __restrict__ W2, const float* __restrict__ b2,
    float* __restrict__ out_h)
{
    const int which = blockIdx.y;
    const float* W    = which ? W2 : W1;
    const float* bias = which ? b2 : b1;
    const int rowBase = blockIdx.x * 64;
    const int tid = threadIdx.x;
    const int maxr = NNODES - rowBase;

    // Fill: 2048 float4 reads; each writes two 16B k-pair entries.
    const float4* A4 = (const float4*)(A + (long)rowBase * DD);
    #pragma unroll
    for (int i = 0; i < 16; i++) {
        int idx4 = tid + i * 128;
        int row = idx4 >> 5;
        int k2  = (idx4 & 31) << 1;              // covers k = 4*(idx4&31) .. +3
        float4 v = make_float4(0.f, 0.f, 0.f, 0.f);
        if (row < maxr) v = A4[idx4];
        unsigned long long* d0 = &As2[(k2 * PROWS + row) * 2];
        d0[0] = dup2(v.x); d0[1] = dup2(v.y);
        unsigned long long* d1 = &As2[((k2 + 1) * PROWS + row) * 2];
        d1[0] = dup2(v.z); d1[1] = dup2(v.w);
    }
    __syncthreads();

    const int lane = tid & 31;
    const int wz   = tid >> 5;        // warp 0..3
    const int rg   = lane >> 4;       // row parity 0/1
    const int c    = lane & 15;       // col group: cols c*8 .. c*8+7
    const int rowB = wz * 16 + rg;    // thread rows: rowB + 2i

    unsigned long long acc[8][4];
    #pragma unroll
    for (int i = 0; i < 8; i++)
        { acc[i][0] = 0ull; acc[i][1] = 0ull; acc[i][2] = 0ull; acc[i][3] = 0ull; }

    const float* Wc = W + c * 8;
    #pragma unroll 4
    for (int k2 = 0; k2 < KP; k2++) {
        const float* Wk0 = Wc + (long)(k2 * 2) * DD;
        ulonglong2 w00 = *(const ulonglong2*)(Wk0);           // k even, cols c*8..+3
        ulonglong2 w01 = *(const ulonglong2*)(Wk0 + 4);       // k even, cols c*8+4..+7
        ulonglong2 w10 = *(const ulonglong2*)(Wk0 + DD);      // k odd
        ulonglong2 w11 = *(const ulonglong2*)(Wk0 + DD + 4);
        const unsigned long long* slab = &As2[(k2 * PROWS + rowB) * 2];
        #pragma unroll
        for (int i = 0; i < 8; i++) {
            ulonglong2 ap = *(const ulonglong2*)(slab + i * 4);   // rows 2 apart (2*2 u64)
            FMA_F32X2(acc[i][0], ap.x, w00.x);
            FMA_F32X2(acc[i][1], ap.x, w00.y);
            FMA_F32X2(acc[i][2], ap.x, w01.x);
            FMA_F32X2(acc[i][3], ap.x, w01.y);
            FMA_F32X2(acc[i][0], ap.y, w10.x);
            FMA_F32X2(acc[i][1], ap.y, w10.y);
            FMA_F32X2(acc[i][2], ap.y, w11.x);
            FMA_F32X2(acc[i][3], ap.y, w11.y);
        }
    }

    float4 bv0 = *(const float4*)(bias + c * 8);
    float4 bv1 = *(const float4*)(bias + c * 8 + 4);
    #pragma unroll
    for (int i = 0; i < 8; i++) {
        int r = rowB + 2 * i;
        if (r < maxr) {
            int gr = rowBase + r;
            float2 p0 = unpk(acc[i][0]);
            float2 p1 = unpk(acc[i][1]);
            float2 p2 = unpk(acc[i][2]);
            float2 p3 = unpk(acc[i][3]);
            float4 oa = make_float4(p0.x + bv0.x, p0.y + bv0.y, p1.x + bv0.z, p1.y + bv0.w);
            float4 ob = make_float4(p2.x + bv1.x, p2.y + bv1.y, p3.x + bv1.z, p3.y + bv1.w);
            if (which) {
                __half2 h0 = __floats2half2_rn(oa.x, oa.y);
                __half2 h1 = __floats2half2_rn(oa.z, oa.w);
                __half2 h2 = __floats2half2_rn(ob.x, ob.y);
                __half2 h3 = __floats2half2_rn(ob.z, ob.w);
                uint4 pk;
                pk.x = *(unsigned*)&h0; pk.y = *(unsigned*)&h1;
                pk.z = *(unsigned*)&h2; pk.w = *(unsigned*)&h3;
                *(uint4*)&g_conv_h[(long)gr * DD + c * 8] = pk;
            } else {
                *(float4*)(out_h + (long)gr * DD + c * 8)     = oa;
                *(float4*)(out_h + (long)gr * DD + c * 8 + 4) = ob;
            }
        }
    }
}

// ---------------------------------------------------------------- CSR pull + fused epilogue
__global__ __launch_bounds__(256) void k_gather(const float* __restrict__ nodes,
                                                float* __restrict__ out) {
    __shared__ float4 sred[256];
    const int tid  = threadIdx.x;
    const int lane = tid & 31;
    const int wy   = tid >> 5;
    const int r    = blockIdx.x * 8 + wy;
    float4 sum = make_float4(0.f, 0.f, 0.f, 0.f);

    if (r < NNODES) {
        const int start = g_offs[r];
        const int deg   = g_rdeg[r];
        float4 acc = make_float4(0.f, 0.f, 0.f, 0.f);
        int j = 0;
        for (; j + 1 < deg; j += 2) {
            int s0 = g_csr[start + j];
            int s1 = g_csr[start + j + 1];
            float w0 = g_rss[s0];
            float w1 = g_rss[s1];
            uint2 a0 = *(const uint2*)&g_conv_h[(long)s0 * DD + lane * 4];
            uint2 a1 = *(const uint2*)&g_conv_h[(long)s1 * DD + lane * 4];
            float2 p00 = __half22float2(*(__half2*)&a0.x);
            float2 p01 = __half22float2(*(__half2*)&a0.y);
            float2 p10 = __half22float2(*(__half2*)&a1.x);
            float2 p11 = __half22float2(*(__half2*)&a1.y);
            acc.x = fmaf(p00.x, w0, fmaf(p10.x, w1, acc.x));
            acc.y = fmaf(p00.y, w0, fmaf(p10.y, w1, acc.y));
            acc.z = fmaf(p01.x, w0, fmaf(p11.x, w1, acc.z));
            acc.w = fmaf(p01.y, w0, fmaf(p11.y, w1, acc.w));
        }
        if (j < deg) {
            int s0 = g_csr[start + j];
            float w0 = g_rss[s0];
            uint2 a0 = *(const uint2*)&g_conv_h[(long)s0 * DD + lane * 4];
            float2 p00 = __half22float2(*(__half2*)&a0.x);
            float2 p01 = __half22float2(*(__half2*)&a0.y);
            acc.x = fmaf(p00.x, w0, acc.x);
            acc.y = fmaf(p00.y, w0, acc.y);
            acc.z = fmaf(p01.x, w0, acc.z);
            acc.w = fmaf(p01.y, w0, acc.w);
        }
        float rs = rsqrtf(fmaxf((float)deg, 1.0f));
        float4 gv = ((const float4*)g_gvec)[lane];
        long off = (long)r * 32 + lane;
        float4 h  = ((float4*)out)[off];
        float4 nd = ((const float4*)nodes)[off];
        float4 o;
        o.x = fmaxf(h.x + acc.x * rs + gv.x, 0.f) + nd.x;
        o.y = fmaxf(h.y + acc.y * rs + gv.y, 0.f) + nd.y;
        o.z = fmaxf(h.z + acc.z * rs + gv.z, 0.f) + nd.z;
        o.w = fmaxf(h.w + acc.w * rs + gv.w, 0.f) + nd.w;
        ((float4*)out)[off] = o;
        sum = o;
    }
    sred[tid] = sum;
    __syncthreads();
    if (wy == 0) {
        float4 s = sred[lane];
        #pragma unroll
        for (int jj = 1; jj < 8; jj++) {
            float4 t = sred[jj * 32 + lane];
            s.x += t.x; s.y += t.y; s.z += t.z; s.w += t.w;
        }
        float* addr = &g_an[lane * 4];
        asm volatile("red.global.add.v4.f32 [%0], {%1,%2,%3,%4};"
                     :: "l"(addr), "f"(s.x), "f"(s.y), "f"(s.z), "f"(s.w)
                     : "memory");
    }
}

// ---------------------------------------------------------------- global update
__global__ void k_global(const float* __restrict__ gl, const float* __restrict__ Wg,
                         const float* __restrict__ bg, float* __restrict__ outg) {
    __shared__ float red[2 * DD];
    int c = blockIdx.x, t = threadIdx.x;
    float x = (t < DD) ? g_an[t] : gl[t - DD];
    red[t] = x * Wg[t * DD + c];
    __syncthreads();
    if (t < 128) red[t] += red[t + 128];
    __syncthreads();
    if (t < 64) red[t] += red[t + 64];
    __syncthreads();
    if (t < 32) {
        float v = red[t] + red[t + 32];
        #pragma unroll
        for (int o = 16; o > 0; o >>= 1) v += __shfl_down_sync(0xffffffff, v, o);
        if (t == 0) outg[c] = gl[c] + fmaxf(v + bg[c], 0.f);
    }
}

// ---------------------------------------------------------------- launch (forked graph)
extern "C" void kernel_launch(void* const* d_in, const int* in_sizes, int n_in,
                              void* d_out, int out_size) {
    const float* nodes    = (const float*)d_in[0];
    const float* globals_ = (const float*)d_in[1];
    const int*   senders   = (const int*)d_in[2];
    const int*   receivers = (const int*)d_in[3];
    const float* W1w = (const float*)d_in[4];
    const float* W1b = (const float*)d_in[5];
    const float* W2w = (const float*)d_in[6];
    const float* W2b = (const float*)d_in[7];
    const float* W3w = (const float*)d_in[8];
    const float* W3b = (const float*)d_in[9];
    const float* Wgw = (const float*)d_in[10];
    const float* Wgb = (const float*)d_in[11];
    float* out = (float*)d_out;

    static cudaStream_t s1 = nullptr;
    static cudaEvent_t evRoot = nullptr, evSide = nullptr;
    if (s1 == nullptr) {
        cudaFuncSetAttribute(k_gemm, cudaFuncAttributeMaxDynamicSharedMemorySize, GEMM_SMEM);
        cudaStreamCreateWithFlags(&s1, cudaStreamNonBlocking);
        cudaEventCreateWithFlags(&evRoot, cudaEventDisableTiming);
        cudaEventCreateWithFlags(&evSide, cudaEventDisableTiming);
    }

    // fork
    cudaEventRecord(evRoot, 0);
    cudaStreamWaitEvent(s1, evRoot, 0);

    // side chain part 1 (s1): submissions #1-#3
    k_zero<<<(NNODES + 255) / 256, 256, 0, s1>>>(globals_, W3w, W3b);
    k_deg<<<(NEDGES + 255) / 256, 256, 0, s1>>>(senders, receivers);
    k_scanA<<<SCAN_BLK, 1024, 0, s1>>>();

    // main: dual GEMM — submission #4 (profiler target)
    dim3 gg((NNODES + 63) / 64, 2);
    k_gemm<<<gg, 128, GEMM_SMEM>>>(nodes, W1w, W1b, W2w, W2b, out);

    // side chain part 2 (s1)
    k_scanB<<<1, 128, 0, s1>>>();
    k_scanC<<<(NNODES + 255) / 256, 256, 0, s1>>>();
    k_scatter<<<(NEDGES + 255) / 256, 256, 0, s1>>>(senders, receivers);
    cudaEventRecord(evSide, s1);

    // join -> pull-aggregate + fused epilogue -> global update
    cudaStreamWaitEvent(0, evSide, 0);
    k_gather<<<(NNODES + 7) / 8, 256>>>(nodes, out);
    k_global<<<DD, 2 * DD>>>(globals_, Wgw, Wgb, out + (long)NNODES * DD);
}